// round 9
// baseline (speedup 1.0000x reference)
#include <cuda_runtime.h>
#include <cuda_fp16.h>
#include <mma.h>
#include <cstdint>

using namespace nvcuda;

#define F1 128
#define F2 64
#define MAX_NODES 100000
#define MAX_EDGES 3200000
#define CSR_BLOCKS 256

// ---------------------------------------------------------------------------
// Device-global scratch (allocation-free per harness rules)
// ---------------------------------------------------------------------------
__device__ __half g_y[(size_t)MAX_NODES * F1];
__device__ float g_h[(size_t)MAX_NODES * F1];
__device__ unsigned long long g_edges[MAX_EDGES]; // packed (col, val) sorted by row
__device__ int g_cnt[MAX_NODES];
__device__ int g_ptrE[MAX_NODES];
__device__ int g_bsum[128];
__device__ int g_bsumE[128];
__device__ int g_ptr[MAX_NODES + 1];
__device__ int g_work[MAX_NODES];

// software grid barrier state (count returns to 0 after each barrier; gen is a
// monotone counter — work per call is identical, so determinism holds)
__device__ unsigned g_bar_count = 0;
__device__ unsigned g_bar_gen = 0;

__device__ __forceinline__ void grid_barrier(unsigned nblocks) {
    __syncthreads();
    if (threadIdx.x == 0) {
        volatile unsigned* genp = &g_bar_gen;
        unsigned gen = *genp;
        __threadfence();  // make this block's phase writes visible before arrival
        if (atomicAdd(&g_bar_count, 1u) == nblocks - 1u) {
            g_bar_count = 0u;
            __threadfence();
            *genp = gen + 1u;
        } else {
            while (*genp == gen) __nanosleep(64);
        }
    }
    __syncthreads();
}

// ---------------------------------------------------------------------------
// Fused CSR build: zero -> hist -> scan1 -> scan2 -> scan3 -> scatter,
// one persistent kernel, software grid barriers between phases.
// Cross-block cross-phase reads use __ldcg (L2) to dodge stale L1.
// ---------------------------------------------------------------------------
__global__ __launch_bounds__(256) void csr_build_kernel(const int* __restrict__ rows,
                                                        const int* __restrict__ cols,
                                                        const float* __restrict__ vals,
                                                        int n_nodes, int n_edges) {
    const unsigned nb = gridDim.x;
    const int t = threadIdx.x;
    const int gid = blockIdx.x * 256 + t;
    const int gsz = nb * 256;
    __shared__ int s[256];

    // --- phase 1: zero counts ---
    for (int i = gid; i < n_nodes; i += gsz) g_cnt[i] = 0;
    grid_barrier(nb);

    // --- phase 2: histogram ---
    for (int e = gid; e < n_edges; e += gsz)
        atomicAdd(&g_cnt[__ldg(rows + e)], 1);
    grid_barrier(nb);

    // --- phase 3: per-chunk exclusive scan (1024 elems per chunk) ---
    const int nb_scan = (n_nodes + 1023) >> 10;
    for (int chunk = blockIdx.x; chunk < nb_scan; chunk += nb) {
        __syncthreads();
        const int base = chunk * 1024 + t * 4;
        int v[4];
#pragma unroll
        for (int j = 0; j < 4; j++)
            v[j] = (base + j < n_nodes) ? __ldcg(&g_cnt[base + j]) : 0;
        int tsum = v[0] + v[1] + v[2] + v[3];
        s[t] = tsum;
        __syncthreads();
        for (int off = 1; off < 256; off <<= 1) {
            int x = 0;
            if (t >= off) x = s[t - off];
            __syncthreads();
            if (t >= off) s[t] += x;
            __syncthreads();
        }
        int run = s[t] - tsum;
#pragma unroll
        for (int j = 0; j < 4; j++) {
            if (base + j < n_nodes) g_ptrE[base + j] = run;
            run += v[j];
        }
        if (t == 255) g_bsum[chunk] = s[255];
    }
    grid_barrier(nb);

    // --- phase 4: scan of chunk sums (block 0 only) ---
    if (blockIdx.x == 0) {
        const int base = t * 4;
        int v[4];
#pragma unroll
        for (int j = 0; j < 4; j++)
            v[j] = (base + j < nb_scan) ? __ldcg(&g_bsum[base + j]) : 0;
        int tsum = v[0] + v[1] + v[2] + v[3];
        s[t] = tsum;
        __syncthreads();
        for (int off = 1; off < 256; off <<= 1) {
            int x = 0;
            if (t >= off) x = s[t - off];
            __syncthreads();
            if (t >= off) s[t] += x;
            __syncthreads();
        }
        int run = s[t] - tsum;
#pragma unroll
        for (int j = 0; j < 4; j++) {
            if (base + j < nb_scan) g_bsumE[base + j] = run;
            run += v[j];
        }
    }
    grid_barrier(nb);

    // --- phase 5: combine -> row pointers + scatter cursors ---
    for (int i = gid; i < n_nodes; i += gsz) {
        int p = __ldcg(&g_ptrE[i]) + __ldcg(&g_bsumE[i >> 10]);
        g_ptr[i] = p;
        g_work[i] = p;
    }
    if (gid == 0) g_ptr[n_nodes] = n_edges;
    grid_barrier(nb);

    // --- phase 6: scatter edges (atomics read L2 cursors directly) ---
    for (int e = gid; e < n_edges; e += gsz) {
        int r = __ldg(rows + e);
        int pos = atomicAdd(&g_work[r], 1);
        unsigned long long packed =
            (unsigned long long)(unsigned int)__ldg(cols + e) |
            ((unsigned long long)__float_as_uint(__ldg(vals + e)) << 32);
        g_edges[pos] = packed;
    }
}

// ---------------------------------------------------------------------------
// Pull-based CSR SPMM from fp16 source, fp32 accumulation.
// ---------------------------------------------------------------------------
__global__ __launch_bounds__(256) void csr_spmm128_kernel(const __half* __restrict__ src,
                                                          float* __restrict__ dst,
                                                          int n_nodes) {
    const int lane = threadIdx.x & 31;
    const int row = (blockIdx.x * 256 + threadIdx.x) >> 5;
    if (row >= n_nodes) return;
    const int p0 = __ldg(&g_ptr[row]);
    const int p1 = __ldg(&g_ptr[row + 1]);
    const uint2* s8 = reinterpret_cast<const uint2*>(src);

    float4 acc = make_float4(0.f, 0.f, 0.f, 0.f);
    int e = p0;
    for (; e + 2 <= p1; e += 2) {
        unsigned long long e0 = __ldg(&g_edges[e]);
        unsigned long long e1 = __ldg(&g_edges[e + 1]);
        int c0 = (int)(unsigned int)e0;
        int c1 = (int)(unsigned int)e1;
        float v0 = __uint_as_float((unsigned int)(e0 >> 32));
        float v1 = __uint_as_float((unsigned int)(e1 >> 32));
        uint2 a = __ldg(s8 + (size_t)c0 * 32 + lane);
        uint2 b = __ldg(s8 + (size_t)c1 * 32 + lane);
        float2 a01 = __half22float2(*reinterpret_cast<__half2*>(&a.x));
        float2 a23 = __half22float2(*reinterpret_cast<__half2*>(&a.y));
        float2 b01 = __half22float2(*reinterpret_cast<__half2*>(&b.x));
        float2 b23 = __half22float2(*reinterpret_cast<__half2*>(&b.y));
        acc.x = fmaf(a01.x, v0, fmaf(b01.x, v1, acc.x));
        acc.y = fmaf(a01.y, v0, fmaf(b01.y, v1, acc.y));
        acc.z = fmaf(a23.x, v0, fmaf(b23.x, v1, acc.z));
        acc.w = fmaf(a23.y, v0, fmaf(b23.y, v1, acc.w));
    }
    if (e < p1) {
        unsigned long long e0 = __ldg(&g_edges[e]);
        int c0 = (int)(unsigned int)e0;
        float v0 = __uint_as_float((unsigned int)(e0 >> 32));
        uint2 a = __ldg(s8 + (size_t)c0 * 32 + lane);
        float2 a01 = __half22float2(*reinterpret_cast<__half2*>(&a.x));
        float2 a23 = __half22float2(*reinterpret_cast<__half2*>(&a.y));
        acc.x = fmaf(a01.x, v0, acc.x);
        acc.y = fmaf(a01.y, v0, acc.y);
        acc.z = fmaf(a23.x, v0, acc.z);
        acc.w = fmaf(a23.y, v0, acc.w);
    }
    reinterpret_cast<float4*>(dst)[(size_t)row * 32 + lane] = acc;
}

__global__ __launch_bounds__(256) void csr_spmm64_kernel(const __half* __restrict__ src,
                                                         const float* __restrict__ b2,
                                                         float* __restrict__ dst,
                                                         int n_nodes) {
    const int lane = threadIdx.x & 31;
    const int row = (blockIdx.x * 256 + threadIdx.x) >> 5;
    if (row >= n_nodes) return;
    const int p0 = __ldg(&g_ptr[row]);
    const int p1 = __ldg(&g_ptr[row + 1]);
    const unsigned* s4 = reinterpret_cast<const unsigned*>(src);

    float2 acc = make_float2(0.f, 0.f);
    int e = p0;
    for (; e + 2 <= p1; e += 2) {
        unsigned long long e0 = __ldg(&g_edges[e]);
        unsigned long long e1 = __ldg(&g_edges[e + 1]);
        int c0 = (int)(unsigned int)e0;
        int c1 = (int)(unsigned int)e1;
        float v0 = __uint_as_float((unsigned int)(e0 >> 32));
        float v1 = __uint_as_float((unsigned int)(e1 >> 32));
        unsigned a = __ldg(s4 + (size_t)c0 * 32 + lane);
        unsigned b = __ldg(s4 + (size_t)c1 * 32 + lane);
        float2 af = __half22float2(*reinterpret_cast<__half2*>(&a));
        float2 bf = __half22float2(*reinterpret_cast<__half2*>(&b));
        acc.x = fmaf(af.x, v0, fmaf(bf.x, v1, acc.x));
        acc.y = fmaf(af.y, v0, fmaf(bf.y, v1, acc.y));
    }
    if (e < p1) {
        unsigned long long e0 = __ldg(&g_edges[e]);
        int c0 = (int)(unsigned int)e0;
        float v0 = __uint_as_float((unsigned int)(e0 >> 32));
        unsigned a = __ldg(s4 + (size_t)c0 * 32 + lane);
        float2 af = __half22float2(*reinterpret_cast<__half2*>(&a));
        acc.x = fmaf(af.x, v0, acc.x);
        acc.y = fmaf(af.y, v0, acc.y);
    }
    float2 bv = __ldg(reinterpret_cast<const float2*>(b2) + lane);
    acc.x += bv.x;
    acc.y += bv.y;
    reinterpret_cast<float2*>(dst)[(size_t)row * 32 + lane] = acc;
}

// ---------------------------------------------------------------------------
// Tensor-core GEMM (wmma m16n16k16, fp16 in / fp32 acc)
// ---------------------------------------------------------------------------
template <int K, int N, bool RELU_BIAS>
__global__ __launch_bounds__(256) void wmma_gemm_kernel(const float* __restrict__ A,
                                                        const float* __restrict__ W,
                                                        const float* __restrict__ bias,
                                                        __half* __restrict__ Yh,
                                                        int n_rows) {
    constexpr int BM = 128;
    constexpr int BK = 64;
    constexpr int BN = N;
    constexpr int LDA = BK + 8;
    constexpr int LDB = BN + 8;
    constexpr int WN = BN / 32;
    constexpr int WM = 2;

    __shared__ __half As[BM][LDA];
    __shared__ __half Bs[BK][LDB];
    __shared__ float St[8][16][20];

    const int t = threadIdx.x;
    const int warp = t >> 5;
    const int lane = t & 31;
    const int row0 = blockIdx.x * BM;
    const int warpM = warp & 3;
    const int warpN = warp >> 2;

    wmma::fragment<wmma::accumulator, 16, 16, 16, float> acc[WM][WN];
#pragma unroll
    for (int mi = 0; mi < WM; mi++)
#pragma unroll
        for (int ni = 0; ni < WN; ni++) wmma::fill_fragment(acc[mi][ni], 0.0f);

    for (int k0 = 0; k0 < K; k0 += BK) {
        {
            const int quad = t & 15;
            const int rsub = t >> 4;
#pragma unroll
            for (int p = 0; p < BM / 16; p++) {
                const int row = p * 16 + rsub;
                const int grow = row0 + row;
                float4 av = make_float4(0.f, 0.f, 0.f, 0.f);
                if (grow < n_rows)
                    av = *reinterpret_cast<const float4*>(A + (size_t)grow * K + k0 + quad * 4);
                if (RELU_BIAS) {
                    float4 bv = *reinterpret_cast<const float4*>(bias + k0 + quad * 4);
                    av.x = fmaxf(av.x + bv.x, 0.f);
                    av.y = fmaxf(av.y + bv.y, 0.f);
                    av.z = fmaxf(av.z + bv.z, 0.f);
                    av.w = fmaxf(av.w + bv.w, 0.f);
                }
                __half2 h01 = __float22half2_rn(make_float2(av.x, av.y));
                __half2 h23 = __float22half2_rn(make_float2(av.z, av.w));
                uint2 o;
                o.x = *reinterpret_cast<unsigned*>(&h01);
                o.y = *reinterpret_cast<unsigned*>(&h23);
                *reinterpret_cast<uint2*>(&As[row][quad * 4]) = o;
            }
        }
        {
            constexpr int QPR = BN / 4;
            constexpr int RPP = 256 / QPR;
            const int quad = t % QPR;
            const int rsub = t / QPR;
#pragma unroll
            for (int p = 0; p < BK / RPP; p++) {
                const int row = p * RPP + rsub;
                float4 wv = *reinterpret_cast<const float4*>(W + (size_t)(k0 + row) * BN + quad * 4);
                __half2 h01 = __float22half2_rn(make_float2(wv.x, wv.y));
                __half2 h23 = __float22half2_rn(make_float2(wv.z, wv.w));
                uint2 o;
                o.x = *reinterpret_cast<unsigned*>(&h01);
                o.y = *reinterpret_cast<unsigned*>(&h23);
                *reinterpret_cast<uint2*>(&Bs[row][quad * 4]) = o;
            }
        }
        __syncthreads();

#pragma unroll
        for (int kk = 0; kk < BK; kk += 16) {
            wmma::fragment<wmma::matrix_a, 16, 16, 16, __half, wmma::row_major> af[WM];
            wmma::fragment<wmma::matrix_b, 16, 16, 16, __half, wmma::row_major> bf[WN];
#pragma unroll
            for (int mi = 0; mi < WM; mi++)
                wmma::load_matrix_sync(af[mi], &As[warpM * 32 + mi * 16][kk], LDA);
#pragma unroll
            for (int ni = 0; ni < WN; ni++)
                wmma::load_matrix_sync(bf[ni], &Bs[kk][warpN * (BN / 2) + ni * 16], LDB);
#pragma unroll
            for (int mi = 0; mi < WM; mi++)
#pragma unroll
                for (int ni = 0; ni < WN; ni++)
                    wmma::mma_sync(acc[mi][ni], af[mi], bf[ni], acc[mi][ni]);
        }
        __syncthreads();
    }

#pragma unroll
    for (int mi = 0; mi < WM; mi++) {
#pragma unroll
        for (int ni = 0; ni < WN; ni++) {
            wmma::store_matrix_sync(&St[warp][0][0], acc[mi][ni], 20, wmma::mem_row_major);
            __syncwarp();
            const int r = lane >> 1;
            const int cq = (lane & 1) * 8;
            const int grow = row0 + warpM * 32 + mi * 16 + r;
            if (grow < n_rows) {
                float* sp = &St[warp][r][cq];
                __half2 h0 = __float22half2_rn(make_float2(sp[0], sp[1]));
                __half2 h1 = __float22half2_rn(make_float2(sp[2], sp[3]));
                __half2 h2 = __float22half2_rn(make_float2(sp[4], sp[5]));
                __half2 h3 = __float22half2_rn(make_float2(sp[6], sp[7]));
                uint4 o;
                o.x = *reinterpret_cast<unsigned*>(&h0);
                o.y = *reinterpret_cast<unsigned*>(&h1);
                o.z = *reinterpret_cast<unsigned*>(&h2);
                o.w = *reinterpret_cast<unsigned*>(&h3);
                const int gcol = warpN * (BN / 2) + ni * 16 + cq;
                *reinterpret_cast<uint4*>(Yh + (size_t)grow * N + gcol) = o;
            }
            __syncwarp();
        }
    }
}

// ---------------------------------------------------------------------------
// launch: fork gemm1 onto a side stream, concurrent with the CSR build.
// Stream/events are host-side resources created once (no device allocations).
// ---------------------------------------------------------------------------
extern "C" void kernel_launch(void* const* d_in, const int* in_sizes, int n_in,
                              void* d_out, int out_size) {
    const float* x = (const float*)d_in[0];
    const int* adj_rows = (const int*)d_in[1];
    const int* adj_cols = (const int*)d_in[2];
    const float* adj_vals = (const float*)d_in[3];
    const float* W1 = (const float*)d_in[4];
    const float* b1 = (const float*)d_in[5];
    const float* W2 = (const float*)d_in[6];
    const float* b2 = (const float*)d_in[7];
    float* out = (float*)d_out;

    const int n_nodes = in_sizes[0] / 256;
    const int n_edges = in_sizes[1];

    void* yp_ = nullptr;
    void* hp_ = nullptr;
    cudaGetSymbolAddress(&yp_, g_y);
    cudaGetSymbolAddress(&hp_, g_h);
    __half* y = (__half*)yp_;
    float* h = (float*)hp_;
    __half* z = y;  // reuse g_y (fp16) for z after spmm1 consumed y

    static cudaStream_t side = [] {
        cudaStream_t s;
        cudaStreamCreateWithFlags(&s, cudaStreamNonBlocking);
        return s;
    }();
    static cudaEvent_t evFork = [] {
        cudaEvent_t e;
        cudaEventCreateWithFlags(&e, cudaEventDisableTiming);
        return e;
    }();
    static cudaEvent_t evJoin = [] {
        cudaEvent_t e;
        cudaEventCreateWithFlags(&e, cudaEventDisableTiming);
        return e;
    }();

    // fork: gemm1 runs on 'side' concurrently with the CSR build on stream 0
    cudaEventRecord(evFork, 0);
    cudaStreamWaitEvent(side, evFork, 0);
    wmma_gemm_kernel<256, F1, false>
        <<<(n_nodes + 127) / 128, 256, 0, side>>>(x, W1, nullptr, y, n_nodes);

    csr_build_kernel<<<CSR_BLOCKS, 256>>>(adj_rows, adj_cols, adj_vals, n_nodes, n_edges);

    // join: spmm1 needs both y (side) and CSR (stream 0)
    cudaEventRecord(evJoin, side);
    cudaStreamWaitEvent(0, evJoin, 0);

    // h = spmm(y) (fp32 accum)
    csr_spmm128_kernel<<<(n_nodes * 32 + 255) / 256, 256>>>(y, h, n_nodes);
    // z = fp16(relu(h + b1) @ W2)
    wmma_gemm_kernel<F1, F2, true><<<(n_nodes + 127) / 128, 256>>>(h, W2, b1, z, n_nodes);
    // out = spmm(z) + b2
    csr_spmm64_kernel<<<(n_nodes * 32 + 255) / 256, 256>>>(z, b2, out, n_nodes);
}

// round 12
// speedup vs baseline: 1.0903x; 1.0903x over previous
#include <cuda_runtime.h>
#include <cuda_fp16.h>
#include <mma.h>
#include <cstdint>

using namespace nvcuda;

#define F1 128
#define F2 64
#define MAX_NODES 100000
#define MAX_EDGES 3200000

// ---------------------------------------------------------------------------
// Device-global scratch (allocation-free per harness rules)
// ---------------------------------------------------------------------------
__device__ __half g_y[(size_t)MAX_NODES * F1];
__device__ float g_h[(size_t)MAX_NODES * F1];
__device__ unsigned long long g_edges[MAX_EDGES]; // packed (col, val) sorted by row
__device__ int g_cnt[MAX_NODES];
__device__ int g_ptrE[MAX_NODES];
__device__ int g_bsum[128];
__device__ int g_ptr[MAX_NODES + 1];
__device__ int g_work[MAX_NODES];

// ---------------------------------------------------------------------------
// CSR build: zero counts -> histogram -> scan1 -> scan23 -> scatter
// ---------------------------------------------------------------------------
__global__ __launch_bounds__(256) void zero_cnt_kernel(int n_nodes) {
    int i = blockIdx.x * 256 + threadIdx.x;
    if (i < n_nodes) g_cnt[i] = 0;
}

__global__ __launch_bounds__(256) void hist_kernel(const int* __restrict__ rows,
                                                   int n_edges) {
    int e = blockIdx.x * 256 + threadIdx.x;
    if (e < n_edges) atomicAdd(&g_cnt[__ldg(rows + e)], 1);
}

// Exclusive scan of 1024 elements per block (256 threads x 4).
__global__ __launch_bounds__(256) void scan1_kernel(int n) {
    __shared__ int s[256];
    const int t = threadIdx.x;
    const int base = blockIdx.x * 1024 + t * 4;
    int v[4];
#pragma unroll
    for (int j = 0; j < 4; j++) v[j] = (base + j < n) ? g_cnt[base + j] : 0;
    int tsum = v[0] + v[1] + v[2] + v[3];
    s[t] = tsum;
    __syncthreads();
    for (int off = 1; off < 256; off <<= 1) {
        int x = 0;
        if (t >= off) x = s[t - off];
        __syncthreads();
        if (t >= off) s[t] += x;
        __syncthreads();
    }
    int run = s[t] - tsum;  // exclusive
#pragma unroll
    for (int j = 0; j < 4; j++) {
        if (base + j < n) g_ptrE[base + j] = run;
        run += v[j];
    }
    if (t == 255) g_bsum[blockIdx.x] = s[255];
}

// Merged scan2+scan3: every block re-scans the (<=128) chunk sums in smem,
// then combines with the per-chunk exclusive scan -> row ptrs + cursors.
__global__ __launch_bounds__(256) void scan23_kernel(int n_nodes, int n_edges,
                                                     int nb_scan) {
    __shared__ int sb[128];
    const int t = threadIdx.x;
    if (t < 128) sb[t] = (t < nb_scan) ? g_bsum[t] : 0;
    __syncthreads();
    for (int off = 1; off < 128; off <<= 1) {
        int x = 0;
        if (t < 128 && t >= off) x = sb[t - off];
        __syncthreads();
        if (t < 128 && t >= off) sb[t] += x;
        __syncthreads();
    }
    // sb is now an inclusive scan; exclusive prefix of chunk c = sb[c-1]
    const int i = blockIdx.x * 256 + t;
    if (i < n_nodes) {
        const int c = i >> 10;
        const int b = (c == 0) ? 0 : sb[c - 1];
        const int p = g_ptrE[i] + b;
        g_ptr[i] = p;
        g_work[i] = p;
    }
    if (i == 0) g_ptr[n_nodes] = n_edges;
}

__global__ __launch_bounds__(256) void scatter_kernel(const int* __restrict__ rows,
                                                      const int* __restrict__ cols,
                                                      const float* __restrict__ vals,
                                                      int n_edges) {
    int e = blockIdx.x * 256 + threadIdx.x;
    if (e < n_edges) {
        int r = __ldg(rows + e);
        int pos = atomicAdd(&g_work[r], 1);
        unsigned long long packed =
            (unsigned long long)(unsigned int)__ldg(cols + e) |
            ((unsigned long long)__float_as_uint(__ldg(vals + e)) << 32);
        g_edges[pos] = packed;
    }
}

// ---------------------------------------------------------------------------
// Pull-based CSR SPMM from fp16 source, fp32 accumulation.
// ---------------------------------------------------------------------------
__global__ __launch_bounds__(256) void csr_spmm128_kernel(const __half* __restrict__ src,
                                                          float* __restrict__ dst,
                                                          int n_nodes) {
    const int lane = threadIdx.x & 31;
    const int row = (blockIdx.x * 256 + threadIdx.x) >> 5;
    if (row >= n_nodes) return;
    const int p0 = __ldg(&g_ptr[row]);
    const int p1 = __ldg(&g_ptr[row + 1]);
    const uint2* s8 = reinterpret_cast<const uint2*>(src);

    float4 acc = make_float4(0.f, 0.f, 0.f, 0.f);
    int e = p0;
    for (; e + 2 <= p1; e += 2) {
        unsigned long long e0 = __ldg(&g_edges[e]);
        unsigned long long e1 = __ldg(&g_edges[e + 1]);
        int c0 = (int)(unsigned int)e0;
        int c1 = (int)(unsigned int)e1;
        float v0 = __uint_as_float((unsigned int)(e0 >> 32));
        float v1 = __uint_as_float((unsigned int)(e1 >> 32));
        uint2 a = __ldg(s8 + (size_t)c0 * 32 + lane);
        uint2 b = __ldg(s8 + (size_t)c1 * 32 + lane);
        float2 a01 = __half22float2(*reinterpret_cast<__half2*>(&a.x));
        float2 a23 = __half22float2(*reinterpret_cast<__half2*>(&a.y));
        float2 b01 = __half22float2(*reinterpret_cast<__half2*>(&b.x));
        float2 b23 = __half22float2(*reinterpret_cast<__half2*>(&b.y));
        acc.x = fmaf(a01.x, v0, fmaf(b01.x, v1, acc.x));
        acc.y = fmaf(a01.y, v0, fmaf(b01.y, v1, acc.y));
        acc.z = fmaf(a23.x, v0, fmaf(b23.x, v1, acc.z));
        acc.w = fmaf(a23.y, v0, fmaf(b23.y, v1, acc.w));
    }
    if (e < p1) {
        unsigned long long e0 = __ldg(&g_edges[e]);
        int c0 = (int)(unsigned int)e0;
        float v0 = __uint_as_float((unsigned int)(e0 >> 32));
        uint2 a = __ldg(s8 + (size_t)c0 * 32 + lane);
        float2 a01 = __half22float2(*reinterpret_cast<__half2*>(&a.x));
        float2 a23 = __half22float2(*reinterpret_cast<__half2*>(&a.y));
        acc.x = fmaf(a01.x, v0, acc.x);
        acc.y = fmaf(a01.y, v0, acc.y);
        acc.z = fmaf(a23.x, v0, acc.z);
        acc.w = fmaf(a23.y, v0, acc.w);
    }
    reinterpret_cast<float4*>(dst)[(size_t)row * 32 + lane] = acc;
}

__global__ __launch_bounds__(256) void csr_spmm64_kernel(const __half* __restrict__ src,
                                                         const float* __restrict__ b2,
                                                         float* __restrict__ dst,
                                                         int n_nodes) {
    const int lane = threadIdx.x & 31;
    const int row = (blockIdx.x * 256 + threadIdx.x) >> 5;
    if (row >= n_nodes) return;
    const int p0 = __ldg(&g_ptr[row]);
    const int p1 = __ldg(&g_ptr[row + 1]);
    const unsigned* s4 = reinterpret_cast<const unsigned*>(src);

    float2 acc = make_float2(0.f, 0.f);
    int e = p0;
    for (; e + 2 <= p1; e += 2) {
        unsigned long long e0 = __ldg(&g_edges[e]);
        unsigned long long e1 = __ldg(&g_edges[e + 1]);
        int c0 = (int)(unsigned int)e0;
        int c1 = (int)(unsigned int)e1;
        float v0 = __uint_as_float((unsigned int)(e0 >> 32));
        float v1 = __uint_as_float((unsigned int)(e1 >> 32));
        unsigned a = __ldg(s4 + (size_t)c0 * 32 + lane);
        unsigned b = __ldg(s4 + (size_t)c1 * 32 + lane);
        float2 af = __half22float2(*reinterpret_cast<__half2*>(&a));
        float2 bf = __half22float2(*reinterpret_cast<__half2*>(&b));
        acc.x = fmaf(af.x, v0, fmaf(bf.x, v1, acc.x));
        acc.y = fmaf(af.y, v0, fmaf(bf.y, v1, acc.y));
    }
    if (e < p1) {
        unsigned long long e0 = __ldg(&g_edges[e]);
        int c0 = (int)(unsigned int)e0;
        float v0 = __uint_as_float((unsigned int)(e0 >> 32));
        unsigned a = __ldg(s4 + (size_t)c0 * 32 + lane);
        float2 af = __half22float2(*reinterpret_cast<__half2*>(&a));
        acc.x = fmaf(af.x, v0, acc.x);
        acc.y = fmaf(af.y, v0, acc.y);
    }
    float2 bv = __ldg(reinterpret_cast<const float2*>(b2) + lane);
    acc.x += bv.x;
    acc.y += bv.y;
    reinterpret_cast<float2*>(dst)[(size_t)row * 32 + lane] = acc;
}

// ---------------------------------------------------------------------------
// Tensor-core GEMM (wmma m16n16k16, fp16 in / fp32 acc)
// ---------------------------------------------------------------------------
template <int K, int N, bool RELU_BIAS>
__global__ __launch_bounds__(256) void wmma_gemm_kernel(const float* __restrict__ A,
                                                        const float* __restrict__ W,
                                                        const float* __restrict__ bias,
                                                        __half* __restrict__ Yh,
                                                        int n_rows) {
    constexpr int BM = 128;
    constexpr int BK = 64;
    constexpr int BN = N;
    constexpr int LDA = BK + 8;
    constexpr int LDB = BN + 8;
    constexpr int WN = BN / 32;
    constexpr int WM = 2;

    __shared__ __half As[BM][LDA];
    __shared__ __half Bs[BK][LDB];
    __shared__ float St[8][16][20];

    const int t = threadIdx.x;
    const int warp = t >> 5;
    const int lane = t & 31;
    const int row0 = blockIdx.x * BM;
    const int warpM = warp & 3;
    const int warpN = warp >> 2;

    wmma::fragment<wmma::accumulator, 16, 16, 16, float> acc[WM][WN];
#pragma unroll
    for (int mi = 0; mi < WM; mi++)
#pragma unroll
        for (int ni = 0; ni < WN; ni++) wmma::fill_fragment(acc[mi][ni], 0.0f);

    for (int k0 = 0; k0 < K; k0 += BK) {
        {
            const int quad = t & 15;
            const int rsub = t >> 4;
#pragma unroll
            for (int p = 0; p < BM / 16; p++) {
                const int row = p * 16 + rsub;
                const int grow = row0 + row;
                float4 av = make_float4(0.f, 0.f, 0.f, 0.f);
                if (grow < n_rows)
                    av = *reinterpret_cast<const float4*>(A + (size_t)grow * K + k0 + quad * 4);
                if (RELU_BIAS) {
                    float4 bv = *reinterpret_cast<const float4*>(bias + k0 + quad * 4);
                    av.x = fmaxf(av.x + bv.x, 0.f);
                    av.y = fmaxf(av.y + bv.y, 0.f);
                    av.z = fmaxf(av.z + bv.z, 0.f);
                    av.w = fmaxf(av.w + bv.w, 0.f);
                }
                __half2 h01 = __float22half2_rn(make_float2(av.x, av.y));
                __half2 h23 = __float22half2_rn(make_float2(av.z, av.w));
                uint2 o;
                o.x = *reinterpret_cast<unsigned*>(&h01);
                o.y = *reinterpret_cast<unsigned*>(&h23);
                *reinterpret_cast<uint2*>(&As[row][quad * 4]) = o;
            }
        }
        {
            constexpr int QPR = BN / 4;
            constexpr int RPP = 256 / QPR;
            const int quad = t % QPR;
            const int rsub = t / QPR;
#pragma unroll
            for (int p = 0; p < BK / RPP; p++) {
                const int row = p * RPP + rsub;
                float4 wv = *reinterpret_cast<const float4*>(W + (size_t)(k0 + row) * BN + quad * 4);
                __half2 h01 = __float22half2_rn(make_float2(wv.x, wv.y));
                __half2 h23 = __float22half2_rn(make_float2(wv.z, wv.w));
                uint2 o;
                o.x = *reinterpret_cast<unsigned*>(&h01);
                o.y = *reinterpret_cast<unsigned*>(&h23);
                *reinterpret_cast<uint2*>(&Bs[row][quad * 4]) = o;
            }
        }
        __syncthreads();

#pragma unroll
        for (int kk = 0; kk < BK; kk += 16) {
            wmma::fragment<wmma::matrix_a, 16, 16, 16, __half, wmma::row_major> af[WM];
            wmma::fragment<wmma::matrix_b, 16, 16, 16, __half, wmma::row_major> bf[WN];
#pragma unroll
            for (int mi = 0; mi < WM; mi++)
                wmma::load_matrix_sync(af[mi], &As[warpM * 32 + mi * 16][kk], LDA);
#pragma unroll
            for (int ni = 0; ni < WN; ni++)
                wmma::load_matrix_sync(bf[ni], &Bs[kk][warpN * (BN / 2) + ni * 16], LDB);
#pragma unroll
            for (int mi = 0; mi < WM; mi++)
#pragma unroll
                for (int ni = 0; ni < WN; ni++)
                    wmma::mma_sync(acc[mi][ni], af[mi], bf[ni], acc[mi][ni]);
        }
        __syncthreads();
    }

#pragma unroll
    for (int mi = 0; mi < WM; mi++) {
#pragma unroll
        for (int ni = 0; ni < WN; ni++) {
            wmma::store_matrix_sync(&St[warp][0][0], acc[mi][ni], 20, wmma::mem_row_major);
            __syncwarp();
            const int r = lane >> 1;
            const int cq = (lane & 1) * 8;
            const int grow = row0 + warpM * 32 + mi * 16 + r;
            if (grow < n_rows) {
                float* sp = &St[warp][r][cq];
                __half2 h0 = __float22half2_rn(make_float2(sp[0], sp[1]));
                __half2 h1 = __float22half2_rn(make_float2(sp[2], sp[3]));
                __half2 h2 = __float22half2_rn(make_float2(sp[4], sp[5]));
                __half2 h3 = __float22half2_rn(make_float2(sp[6], sp[7]));
                uint4 o;
                o.x = *reinterpret_cast<unsigned*>(&h0);
                o.y = *reinterpret_cast<unsigned*>(&h1);
                o.z = *reinterpret_cast<unsigned*>(&h2);
                o.w = *reinterpret_cast<unsigned*>(&h3);
                const int gcol = warpN * (BN / 2) + ni * 16 + cq;
                *reinterpret_cast<uint4*>(Yh + (size_t)grow * N + gcol) = o;
            }
            __syncwarp();
        }
    }
}

// ---------------------------------------------------------------------------
// launch: unfused CSR chain (R8-proven) + gemm1 forked onto a side stream.
// ---------------------------------------------------------------------------
extern "C" void kernel_launch(void* const* d_in, const int* in_sizes, int n_in,
                              void* d_out, int out_size) {
    const float* x = (const float*)d_in[0];
    const int* adj_rows = (const int*)d_in[1];
    const int* adj_cols = (const int*)d_in[2];
    const float* adj_vals = (const float*)d_in[3];
    const float* W1 = (const float*)d_in[4];
    const float* b1 = (const float*)d_in[5];
    const float* W2 = (const float*)d_in[6];
    const float* b2 = (const float*)d_in[7];
    float* out = (float*)d_out;

    const int n_nodes = in_sizes[0] / 256;
    const int n_edges = in_sizes[1];

    void* yp_ = nullptr;
    void* hp_ = nullptr;
    cudaGetSymbolAddress(&yp_, g_y);
    cudaGetSymbolAddress(&hp_, g_h);
    __half* y = (__half*)yp_;
    float* h = (float*)hp_;
    __half* z = y;  // reuse g_y (fp16) for z after spmm1 consumed y

    static cudaStream_t side = [] {
        cudaStream_t s;
        cudaStreamCreateWithFlags(&s, cudaStreamNonBlocking);
        return s;
    }();
    static cudaEvent_t evFork = [] {
        cudaEvent_t e;
        cudaEventCreateWithFlags(&e, cudaEventDisableTiming);
        return e;
    }();
    static cudaEvent_t evJoin = [] {
        cudaEvent_t e;
        cudaEventCreateWithFlags(&e, cudaEventDisableTiming);
        return e;
    }();

    const int nb_scan = (n_nodes + 1023) / 1024;
    const int eb = (n_edges + 255) / 256;
    const int nb_nodes = (n_nodes + 255) / 256;

    // fork: gemm1 on 'side', concurrent with the CSR chain on stream 0
    cudaEventRecord(evFork, 0);
    cudaStreamWaitEvent(side, evFork, 0);
    wmma_gemm_kernel<256, F1, false>
        <<<(n_nodes + 127) / 128, 256, 0, side>>>(x, W1, nullptr, y, n_nodes);
    cudaEventRecord(evJoin, side);

    // CSR chain (stream 0)
    zero_cnt_kernel<<<nb_nodes, 256>>>(n_nodes);
    hist_kernel<<<eb, 256>>>(adj_rows, n_edges);
    scan1_kernel<<<nb_scan, 256>>>(n_nodes);
    scan23_kernel<<<nb_nodes + 1, 256>>>(n_nodes, n_edges, nb_scan);
    scatter_kernel<<<eb, 256>>>(adj_rows, adj_cols, adj_vals, n_edges);

    // join: spmm1 needs both y (side) and CSR (stream 0)
    cudaStreamWaitEvent(0, evJoin, 0);

    // h = spmm(y) (fp32 accum)
    csr_spmm128_kernel<<<(n_nodes * 32 + 255) / 256, 256>>>(y, h, n_nodes);
    // z = fp16(relu(h + b1) @ W2)
    wmma_gemm_kernel<F1, F2, true><<<(n_nodes + 127) / 128, 256>>>(h, W2, b1, z, n_nodes);
    // out = spmm(z) + b2
    csr_spmm64_kernel<<<(n_nodes * 32 + 255) / 256, 256>>>(z, b2, out, n_nodes);
}